// round 17
// baseline (speedup 1.0000x reference)
#include <cuda_runtime.h>
#include <cstdint>

// Problem constants (B=1024, T=4096, N=2048, K=16, M=2^16)
#define T_DIM   4096
#define N_DIM   2048
#define K_DIM   16
#define B_DIM   1024
#define BW_DIM  (B_DIM / 32)     // 32 b-words per bit-plane
#define GTHREADS 1024            // 2 neurons per CTA, 1 item/thread/neuron

// Bit-plane transposed input, layout [bw][t]: tbit[bw*T + t], bit (b&31) = input[b][t].
__device__ unsigned tbit[BW_DIM * T_DIM];
// Bit-packed result: outbitT[n][w], bit (b&31) of word w = result(b, n). 256 KB.
__device__ unsigned outbitT[N_DIM * BW_DIM];

// 5-stage warp bit-matrix transpose (32x32).
__device__ __forceinline__ unsigned warp_bit_transpose(unsigned x, int lane) {
#pragma unroll
    for (int k = 16; k >= 1; k >>= 1) {
        unsigned mask = (k == 16) ? 0xFFFF0000u :
                        (k ==  8) ? 0xFF00FF00u :
                        (k ==  4) ? 0xF0F0F0F0u :
                        (k ==  2) ? 0xCCCCCCCCu : 0xAAAAAAAAu;
        unsigned y = __shfl_xor_sync(0xFFFFFFFFu, x, k);
        if ((lane & k) == 0) x = (x & ~mask) | ((y << k) &  mask);
        else                 x = (x &  mask) | ((y >> k) & ~mask);
    }
    return x;
}

// Pack v3 (frozen): one warp per 16b x 32t HALF-tile.
__global__ void pack_transpose_kernel(const int* __restrict__ in) {
    int ht   = blockIdx.x * (blockDim.x >> 5) + (threadIdx.x >> 5);
    int lane = threadIdx.x & 31;
    if (ht >= BW_DIM * (T_DIM / 32) * 2) return;
    int half = ht & 1;
    int tile = ht >> 1;
    int bb = tile >> 7;
    int wt = tile & 127;
    int b0 = bb * 32 + half * 16;

    int v[16];
    const int* base = in + (size_t)b0 * T_DIM + wt * 32 + lane;
#pragma unroll
    for (int i = 0; i < 16; ++i) v[i] = base[(size_t)i * T_DIM];

    unsigned rw = 0;
#pragma unroll
    for (int i = 0; i < 16; ++i) {
        unsigned w = __ballot_sync(0xFFFFFFFFu, v[i] != 0);
        if (lane == i) rw = w;
    }
    unsigned tx = warp_bit_transpose(rw, lane);
    size_t word = (size_t)bb * T_DIM + wt * 32 + lane;
    ((unsigned short*)tbit)[word * 2 + half] = (unsigned short)(tx & 0xFFFFu);
}

__device__ __forceinline__ int ldcg_i32(const int* p) {
    int v;
    asm volatile("ld.global.cg.b32 %0, [%1];" : "=r"(v) : "l"(p));
    return v;
}

// TWO neurons per CTA (amortizes barriers/scan 2x). Combined counting sort
// over 512 buckets: key = (neuron_j << 8) | (addr >> 8). Item encoding:
// (j<<26) | (b<<16) | addr.
__global__ __launch_bounds__(GTHREADS)
void ram_gather_kernel(const int* __restrict__ conn,     // [N, K]
                       const int* __restrict__ memory)   // [N, M]
{
    const int n0   = blockIdx.x * 2;
    const int tid  = threadIdx.x;
    const int lane = tid & 31;
    const int warp = tid >> 5;

    __shared__ unsigned cnt[512];
    __shared__ unsigned head[512];
    __shared__ unsigned wsum[16];
    __shared__ unsigned sorted[2 * B_DIM];      // (j<<26)|(b<<16)|addr
    __shared__ unsigned char res[2 * B_DIM];

    if (tid < 512) cnt[tid] = 0;

    // conn words for both neurons (L1-hot; lanes 0..15 hold K indices)
    int myc0 = (lane < K_DIM) ? __ldg(&conn[n0 * K_DIM + lane])       : 0;
    int myc1 = (lane < K_DIM) ? __ldg(&conn[(n0 + 1) * K_DIM + lane]) : 0;
    __syncthreads();   // cnt zeroed

    // ---- Build addresses (one bit-transpose per 32 items) + histogram ----
    const int b  = tid;              // each thread owns batch b for both neurons
    const int bw = b >> 5;           // constant per warp
    unsigned myA[2], myR[2];
#pragma unroll
    for (int j = 0; j < 2; ++j) {
        int c = (j == 0) ? myc0 : myc1;
        unsigned w16 = 0;
        if (lane < K_DIM) w16 = __ldg(&tbit[(size_t)bw * T_DIM + c]);
        unsigned a = warp_bit_transpose(w16, lane) & 0xFFFFu;
        myA[j] = ((unsigned)j << 26) | ((unsigned)b << 16) | a;
        myR[j] = atomicAdd(&cnt[(j << 8) | (a >> 8)], 1u);
    }
    __syncthreads();

    // ---- Exclusive scan of 512 counts: warp-shuffle scan ----
    if (tid < 512) {
        unsigned v = cnt[tid];
        unsigned s = v;
#pragma unroll
        for (int d = 1; d < 32; d <<= 1) {
            unsigned t = __shfl_up_sync(0xFFFFFFFFu, s, d);
            if (lane >= d) s += t;
        }
        if (lane == 31) wsum[warp] = s;
        head[tid] = s - v;
    }
    __syncthreads();
    if (tid < 512) {
        unsigned off = 0;
#pragma unroll
        for (int w = 0; w < 16; ++w) off += (w < warp) ? wsum[w] : 0u;
        head[tid] += off;
    }
    __syncthreads();

    // ---- Place items (atomic-free: pos = head[key] + rank) ----
#pragma unroll
    for (int j = 0; j < 2; ++j) {
        unsigned key = (j << 8) | ((myA[j] & 0xFFFFu) >> 8);
        sorted[head[key] + myR[j]] = myA[j];
    }
    __syncthreads();

    // ---- Row-sorted gather: uint2 = 2 adjacent sorted items (same bucket
    //      -> same DRAM row, issued back-to-back in one lane) ----
    uint2 s2 = ((const uint2*)sorted)[tid];
    unsigned j0 = s2.x >> 26,             j1 = s2.y >> 26;
    const int* m0 = memory + ((size_t)(n0 + j0) << 16);
    const int* m1 = memory + ((size_t)(n0 + j1) << 16);
    int v0 = ldcg_i32(m0 + (s2.x & 0xFFFFu));
    int v1 = ldcg_i32(m1 + (s2.y & 0xFFFFu));
    res[(j0 << 10) | ((s2.x >> 16) & 0x3FFu)] = (unsigned char)(v0 & 1);
    res[(j1 << 10) | ((s2.y >> 16) & 0x3FFu)] = (unsigned char)(v1 & 1);
    __syncthreads();

    // ---- Bit-pack: 64 words (2 neurons x 32), each warp handles 2 ----
    for (int w2 = warp; w2 < 2 * BW_DIM; w2 += GTHREADS / 32) {
        int j = w2 >> 5, w = w2 & 31;
        unsigned word = __ballot_sync(0xFFFFFFFFu,
                                      res[(j << 10) | (w * 32 + lane)] != 0);
        if (lane == 0) outbitT[(n0 + j) * BW_DIM + w] = word;
    }
}

// Expand + transpose (frozen): one warp per 32n x 32b bit tile.
__global__ void expand_kernel(float* __restrict__ out) {
    int tile = blockIdx.x * (blockDim.x >> 5) + (threadIdx.x >> 5);
    int lane = threadIdx.x & 31;
    if (tile >= (N_DIM / 32) * BW_DIM) return;
    int nn = tile >> 5;
    int bb = tile & 31;

    unsigned rw = outbitT[(nn * 32 + lane) * BW_DIM + bb];
    unsigned tx = warp_bit_transpose(rw, lane);
#pragma unroll
    for (int j = 0; j < 32; ++j) {
        unsigned wj = __shfl_sync(0xFFFFFFFFu, tx, j);
        out[(size_t)(bb * 32 + j) * N_DIM + nn * 32 + lane] = (float)((wj >> lane) & 1u);
    }
}

extern "C" void kernel_launch(void* const* d_in, const int* in_sizes, int n_in,
                              void* d_out, int out_size) {
    const int* input_bits  = nullptr;
    const int* connections = nullptr;
    const int* memory      = nullptr;

    for (int i = 0; i < n_in; ++i) {
        long long s = in_sizes[i];
        if (s == (long long)N_DIM * K_DIM)            connections = (const int*)d_in[i];
        else if (s == (long long)N_DIM * 65536LL)     memory      = (const int*)d_in[i];
        else                                          input_bits  = (const int*)d_in[i];
    }

    // 32B L2 fetch granularity (measured: gather DRAM traffic 248->88MB;
    // without it the gather would be bandwidth-bound at ~31us+).
    cudaStreamCaptureStatus cap = cudaStreamCaptureStatusNone;
    cudaStreamIsCapturing((cudaStream_t)0, &cap);
    if (cap == cudaStreamCaptureStatusNone) {
        cudaDeviceSetLimit(cudaLimitMaxL2FetchGranularity, 32);
        cudaGetLastError();
    }

    pack_transpose_kernel<<<(BW_DIM * (T_DIM / 32) * 2) / 8, 256>>>(input_bits);
    ram_gather_kernel<<<N_DIM / 2, GTHREADS>>>(connections, memory);
    expand_kernel<<<((N_DIM / 32) * BW_DIM) / 8, 256>>>((float*)d_out);
}